// round 2
// baseline (speedup 1.0000x reference)
#include <cuda_runtime.h>
#include <math.h>

#define B 32
#define L 256
#define EXT 64
#define H 256
#define M 64
#define NMEM 4096
#define NST 32
#define OUT 64

typedef unsigned long long ull;

// ---------------- scratch (device globals; no allocation) ----------------
__device__ float g_xm[B * H];
__device__ float g_kw[B * M], g_e[B * M], g_a[B * M], g_kr[B * M];
__device__ float g_pw[B * 8], g_pr[B * 8];
__device__ float g_score[B * NMEM];
__device__ float g_ww[B * NMEM], g_wr[B * NMEM];
__device__ float g_rpart[B * 16 * M];
__device__ int   g_cnt1[B];
__device__ int   g_cnt2[2 * B];
__device__ int   g_cnt3[B];

// ---------------- helpers ----------------
__device__ __forceinline__ float wredsum(float v) {
    #pragma unroll
    for (int o = 16; o > 0; o >>= 1) v += __shfl_xor_sync(0xffffffffu, v, o);
    return v;
}
__device__ __forceinline__ float gredsum16(float v) {  // reduce within 16-lane half
    #pragma unroll
    for (int o = 8; o > 0; o >>= 1) v += __shfl_xor_sync(0xffffffffu, v, o);
    return v;
}
__device__ __forceinline__ float wredmax(float v) {
    #pragma unroll
    for (int o = 16; o > 0; o >>= 1) v = fmaxf(v, __shfl_xor_sync(0xffffffffu, v, o));
    return v;
}
__device__ __forceinline__ float softplus_f(float x) {
    return (x > 20.f) ? x : log1pf(expf(x));
}
__device__ __forceinline__ float sigmoid_f(float x) {
    return 1.f / (1.f + expf(-x));
}
__device__ __forceinline__ ull pack2(float lo, float hi) {
    ull r; asm("mov.b64 %0,{%1,%2};" : "=l"(r) : "f"(lo), "f"(hi)); return r;
}
__device__ __forceinline__ void unpack2(ull v, float& lo, float& hi) {
    asm("mov.b64 {%0,%1},%2;" : "=f"(lo), "=f"(hi) : "l"(v));
}
__device__ __forceinline__ ull f2fma(ull a, ull b, ull c) {
    ull d; asm("fma.rn.f32x2 %0,%1,%2,%3;" : "=l"(d) : "l"(a), "l"(b), "l"(c)); return d;
}
__device__ __forceinline__ ull f2mul(ull a, ull b) {
    ull d; asm("mul.rn.f32x2 %0,%1,%2;" : "=l"(d) : "l"(a), "l"(b)); return d;
}

// ============ Kernel 1: encoder GEMM + S4D (closed-form sum) + heads ============
// grid (B, H/16), block 256. Warp handles 2 heads (sel = lane>>4), each 16-lane
// half packs 2 states per lane via fp32x2.
__global__ void __launch_bounds__(256) k_encode_scan(
    const float* __restrict__ x, const float* __restrict__ r0,
    const float* __restrict__ sr0, const float* __restrict__ si0,
    const float* __restrict__ encW, const float* __restrict__ encb,
    const float* __restrict__ log_dt, const float* __restrict__ logAr,
    const float* __restrict__ Aim, const float* __restrict__ Cre,
    const float* __restrict__ Cim, const float* __restrict__ Dv,
    const float* __restrict__ writeW, const float* __restrict__ writeb,
    const float* __restrict__ readW,  const float* __restrict__ readb)
{
    __shared__ float xsT[64 * 66];     // transposed x chunk [e][l], stride 66
    __shared__ ull   Wd[128 * 16];     // duplicated enc_W (w,w) per 16 head slots
    __shared__ ull   us2[16 * 64];     // duplicated u (u,u) per head-slot per l
    __shared__ float xsh[H];
    __shared__ float sow[3 * M + 6];
    __shared__ float sorh[M + 6];
    __shared__ int   isLast;

    int b = blockIdx.x, hg = blockIdx.y;
    int t = threadIdx.x, w = t >> 5, lane = t & 31;
    int sel = lane >> 4, p = lane & 15;
    int slot = w * 2 + sel;
    int h = hg * 16 + slot;

    for (int i = t; i < 128 * 16; i += 256) {
        int e = i >> 4, sl = i & 15;
        float wv = encW[e * H + hg * 16 + sl];
        Wd[i] = pack2(wv, wv);
    }
    __syncthreads();

    // effective bias c = enc_b[h] + r0 . enc_W[EXT:,h]
    float c = 0.f;
    #pragma unroll
    for (int m = p; m < M; m += 16) {
        float lo, hi; unpack2(Wd[(EXT + m) * 16 + slot], lo, hi);
        c += r0[b * M + m] * lo;
    }
    c = gredsum16(c) + encb[h];
    ull cdup = pack2(c, c);

    // per-lane S4D constants for states n0=2p, n0+1
    int n0 = 2 * p;
    float dt = expf(log_dt[h]);
    float dAr_s[2], dAi_s[2];
    #pragma unroll
    for (int s = 0; s < 2; s++) {
        int idx = h * NST + n0 + s;
        float ar = -expf(logAr[idx]);
        float ai = Aim[idx];
        float er = expf(dt * ar);
        dAr_s[s] = er * cosf(dt * ai);
        dAi_s[s] = er * sinf(dt * ai);
    }
    ull dAr2  = pack2(dAr_s[0], dAr_s[1]);
    ull dAi2  = pack2(dAi_s[0], dAi_s[1]);
    ull ndAi2 = pack2(-dAi_s[0], -dAi_s[1]);

    ull tr2 = 0, ti2 = 0;   // T recurrence accumulators (packed)
    float usum = 0.f;
    int base = slot * 64;

    for (int ch = 0; ch < 4; ch++) {
        __syncthreads();
        int l0 = ch * 64;
        for (int i = t; i < 64 * 64; i += 256) {
            int rr = i >> 6, cc = i & 63;   // rr = l, cc = e
            xsT[cc * 66 + rr] = x[((b * L) + (l0 + rr)) * EXT + cc];
        }
        __syncthreads();

        // GEMM: lane computes u for l-pair (2pp, 2pp+1) of head `slot`
        #pragma unroll
        for (int q = 0; q < 2; q++) {
            int pp = p + 16 * q;
            ull acc = cdup;
            #pragma unroll
            for (int e = 0; e < EXT; e++)
                acc = f2fma(Wd[e * 16 + slot],
                            *(const ull*)&xsT[e * 66 + 2 * pp], acc);
            float u0, u1; unpack2(acc, u0, u1);
            us2[base + 2 * pp]     = pack2(u0, u0);
            us2[base + 2 * pp + 1] = pack2(u1, u1);
            usum += u0 + u1;
        }
        __syncwarp();

        // T recurrence: t <- dA*t + u, 64 steps
        #pragma unroll 8
        for (int j = 0; j < 64; j++) {
            ull u2 = us2[base + j];
            ull tA = f2fma(ndAi2, ti2, u2);
            ull trn = f2fma(dAr2, tr2, tA);
            ull tB = f2mul(dAr2, ti2);
            ti2 = f2fma(dAi2, tr2, tB);
            tr2 = trn;
        }
        __syncwarp();
    }

    usum = gredsum16(usum);   // per-head sum of u, broadcast in group

    // closed form: sum_l s_l = Geo*s0 + (-1/A) * (sum_u - dA*T)
    float Trp[2], Tip[2];
    unpack2(tr2, Trp[0], Trp[1]);
    unpack2(ti2, Tip[0], Tip[1]);
    float val = 0.f;
    #pragma unroll
    for (int s = 0; s < 2; s++) {
        int idx = h * NST + n0 + s;
        float ar = -expf(logAr[idx]);
        float ai = Aim[idx];
        float dar = dAr_s[s], dai = dAi_s[s];
        float xr = dar * Trp[s] - dai * Tip[s];
        float xi = dai * Trp[s] + dar * Tip[s];
        float wr = usum - xr, wi = -xi;
        float den = ar * ar + ai * ai;
        float invr = -ar / den, invi = ai / den;
        float Sr = invr * wr - invi * wi;
        float Si = invr * wi + invi * wr;
        // s0 term (s0 is zero in practice but handle generally)
        float s0r = sr0[b * H * NST + idx], s0i = si0[b * H * NST + idx];
        if (s0r != 0.f || s0i != 0.f) {
            float eL = expf((float)L * dt * ar);
            float phi = (float)L * dt * ai;
            float dALr = eL * cosf(phi), dALi = eL * sinf(phi);
            float numr = 1.f - dALr, numi = -dALi;
            float omr = 1.f - dar, omi = -dai;
            float r2 = omr * omr + omi * omi;
            float qr = (numr * omr + numi * omi) / r2;
            float qi = (numi * omr - numr * omi) / r2;
            float gr = dar * qr - dai * qi;
            float gi = dai * qr + dar * qi;
            Sr += gr * s0r - gi * s0i;
            Si += gr * s0i + gi * s0r;
        }
        val += Cre[idx] * Sr - Cim[idx] * Si;
    }
    val = gredsum16(val);
    if (p == 0)
        g_xm[b * H + h] = (2.f * val + (Dv[h] + 1.f) * usum) * (1.f / (float)L);

    // ---- fused heads: last block of this batch runs head projections ----
    __threadfence();
    __syncthreads();
    if (t == 0) {
        int cpl = atomicAdd(&g_cnt1[b], 1);
        isLast = (cpl == 15);
        if (cpl == 15) g_cnt1[b] = 0;
    }
    __syncthreads();
    if (!isLast) return;
    __threadfence();

    xsh[t] = g_xm[b * H + t];
    __syncthreads();

    for (int jj = t; jj < 268; jj += 256) {
        if (jj < 198) {
            float acc = writeb[jj];
            for (int hh = 0; hh < H; hh++) acc = fmaf(xsh[hh], writeW[hh * 198 + jj], acc);
            sow[jj] = acc;
        } else {
            int j = jj - 198;
            float acc = readb[j];
            for (int hh = 0; hh < H; hh++) acc = fmaf(xsh[hh], readW[hh * 70 + j], acc);
            sorh[j] = acc;
        }
    }
    __syncthreads();

    if (t < M) {
        g_kw[b * M + t] = sow[t];
        g_e[b * M + t]  = sigmoid_f(sow[M + 6 + t]);
        g_a[b * M + t]  = sow[2 * M + 6 + t];
        g_kr[b * M + t] = sorh[t];
    } else if (t == M) {
        float beta = softplus_f(sow[M]);
        float g    = sigmoid_f(sow[M + 1]);
        float m3 = fmaxf(sow[M + 2], fmaxf(sow[M + 3], sow[M + 4]));
        float e0 = expf(sow[M + 2] - m3), e1 = expf(sow[M + 3] - m3), e2 = expf(sow[M + 4] - m3);
        float Z = e0 + e1 + e2;
        float gamma = 1.f + softplus_f(sow[M + 5]);
        float nk = 0.f;
        for (int m = 0; m < M; m++) { float v = sow[m]; nk += v * v; }
        g_pw[b * 8 + 0] = beta; g_pw[b * 8 + 1] = g;
        g_pw[b * 8 + 2] = e0 / Z; g_pw[b * 8 + 3] = e1 / Z; g_pw[b * 8 + 4] = e2 / Z;
        g_pw[b * 8 + 5] = gamma; g_pw[b * 8 + 6] = sqrtf(nk);
    } else if (t == M + 1) {
        float beta = softplus_f(sorh[M]);
        float g    = sigmoid_f(sorh[M + 1]);
        float m3 = fmaxf(sorh[M + 2], fmaxf(sorh[M + 3], sorh[M + 4]));
        float e0 = expf(sorh[M + 2] - m3), e1 = expf(sorh[M + 3] - m3), e2 = expf(sorh[M + 4] - m3);
        float Z = e0 + e1 + e2;
        float gamma = 1.f + softplus_f(sorh[M + 5]);
        float nk = 0.f;
        for (int m = 0; m < M; m++) { float v = sorh[m]; nk += v * v; }
        g_pr[b * 8 + 0] = beta; g_pr[b * 8 + 1] = g;
        g_pr[b * 8 + 2] = e0 / Z; g_pr[b * 8 + 3] = e1 / Z; g_pr[b * 8 + 4] = e2 / Z;
        g_pr[b * 8 + 5] = gamma; g_pr[b * 8 + 6] = sqrtf(nk);
    }
}

// ============ Kernel 2/3: cosine scores + fused addressing ============
// grid (B*NMEM/8), block 256. Last block per batch runs the full address phase.
__global__ void __launch_bounds__(256) k_score_addr(
    const float* __restrict__ mem, const float* __restrict__ wprev, int mode)
{
    __shared__ float ks[M], es[M], as_[M];
    __shared__ float sc[NMEM];
    __shared__ float wg[NMEM];
    __shared__ float red[8];
    __shared__ float bcast;
    __shared__ int   isLast;

    int t = threadIdx.x;
    int warp = t >> 5, lane = t & 31;
    int row0 = blockIdx.x * 8;
    int b = row0 >> 12;

    const float* kptr = mode ? (g_kr + b * M) : (g_kw + b * M);
    if (t < M) {
        ks[t] = kptr[t];
        if (mode) { es[t] = g_e[b * M + t]; as_[t] = g_a[b * M + t]; }
    }
    __syncthreads();

    int row = row0 + warp;
    float wv = mode ? g_ww[row] : 0.f;
    float2 v2 = ((const float2*)(mem + (size_t)row * M))[lane];
    if (mode) {
        v2.x = v2.x * (1.f - wv * es[2 * lane])     + wv * as_[2 * lane];
        v2.y = v2.y * (1.f - wv * es[2 * lane + 1]) + wv * as_[2 * lane + 1];
    }
    float dot = v2.x * ks[2 * lane] + v2.y * ks[2 * lane + 1];
    float ss  = v2.x * v2.x + v2.y * v2.y;
    dot = wredsum(dot);
    ss  = wredsum(ss);
    if (lane == 0) {
        const float* pp = mode ? g_pr : g_pw;
        float beta = pp[b * 8 + 0], kn = pp[b * 8 + 6];
        g_score[row] = beta * dot / (sqrtf(ss) * kn + 1e-16f);
    }

    // ---- fused address phase (last block of this batch) ----
    __threadfence();
    __syncthreads();
    if (t == 0) {
        int cpl = atomicAdd(&g_cnt2[mode * B + b], 1);
        isLast = (cpl == 511);
        if (cpl == 511) g_cnt2[mode * B + b] = 0;
    }
    __syncthreads();
    if (!isLast) return;
    __threadfence();

    const float* pp = mode ? g_pr : g_pw;
    float g  = pp[b * 8 + 1];
    float s0 = pp[b * 8 + 2], s1 = pp[b * 8 + 3], s2 = pp[b * 8 + 4];
    float gamma = pp[b * 8 + 5];

    float lm = __int_as_float(0xff800000);
    #pragma unroll
    for (int i = 0; i < 16; i++) {
        int n = t + 256 * i;
        float v = g_score[b * NMEM + n];
        sc[n] = v; lm = fmaxf(lm, v);
    }
    lm = wredmax(lm);
    if (lane == 0) red[warp] = lm;
    __syncthreads();
    if (warp == 0) {
        float v = (lane < 8) ? red[lane] : __int_as_float(0xff800000);
        #pragma unroll
        for (int o = 4; o > 0; o >>= 1) v = fmaxf(v, __shfl_xor_sync(0xffffffffu, v, o));
        if (lane == 0) bcast = v;
    }
    __syncthreads();
    float bm = bcast;

    float ls = 0.f;
    #pragma unroll
    for (int i = 0; i < 16; i++) {
        int n = t + 256 * i;
        float pv = __expf(sc[n] - bm);
        sc[n] = pv; ls += pv;
    }
    ls = wredsum(ls);
    if (lane == 0) red[warp] = ls;
    __syncthreads();
    if (warp == 0) {
        float v = (lane < 8) ? red[lane] : 0.f;
        #pragma unroll
        for (int o = 4; o > 0; o >>= 1) v += __shfl_xor_sync(0xffffffffu, v, o);
        if (lane == 0) bcast = v;
    }
    __syncthreads();
    float gZ = g / bcast;
    float og = 1.f - g;

    #pragma unroll
    for (int i = 0; i < 16; i++) {
        int n = t + 256 * i;
        wg[n] = fmaf(gZ, sc[n], og * wprev[b * NMEM + n]);
    }
    __syncthreads();

    float lp = 0.f;
    #pragma unroll
    for (int i = 0; i < 16; i++) {
        int n = t + 256 * i;
        float wt = s0 * wg[(n - 1) & (NMEM - 1)] + s1 * wg[n] + s2 * wg[(n + 1) & (NMEM - 1)];
        float wp = (wt > 0.f) ? __powf(wt, gamma) : 0.f;
        sc[n] = wp; lp += wp;
    }
    lp = wredsum(lp);
    if (lane == 0) red[warp] = lp;
    __syncthreads();
    if (warp == 0) {
        float v = (lane < 8) ? red[lane] : 0.f;
        #pragma unroll
        for (int o = 4; o > 0; o >>= 1) v += __shfl_xor_sync(0xffffffffu, v, o);
        if (lane == 0) bcast = v + 1e-16f;
    }
    __syncthreads();
    float iZp = 1.f / bcast;

    float* wout = mode ? g_wr : g_ww;
    #pragma unroll
    for (int i = 0; i < 16; i++) {
        int n = t + 256 * i;
        wout[b * NMEM + n] = sc[n] * iZp;
    }
}

// ============ Kernel 4: r = w_r . mem2 + fused decoder ============
// grid (B, 16), block 256
__global__ void __launch_bounds__(256) k_readvec_dec(
    const float* __restrict__ mem, const float* __restrict__ decW,
    const float* __restrict__ decb, float* __restrict__ out)
{
    __shared__ float es[M], as_[M];
    __shared__ float part[4][M];
    __shared__ float xsd[H];
    __shared__ float rs[M];
    __shared__ int   isLast;

    int b = blockIdx.x, chunk = blockIdx.y;
    int t = threadIdx.x, m = t & 63, grp = t >> 6;
    if (t < M) { es[t] = g_e[b * M + t]; as_[t] = g_a[b * M + t]; }
    __syncthreads();

    float acc = 0.f;
    int n0 = chunk * 256;
    for (int n = n0 + grp; n < n0 + 256; n += 4) {
        int row = b * NMEM + n;
        float wwv = g_ww[row], wrv = g_wr[row];
        float v = mem[(size_t)row * M + m];
        float v2 = v * (1.f - wwv * es[m]) + wwv * as_[m];
        acc = fmaf(wrv, v2, acc);
    }
    part[grp][m] = acc;
    __syncthreads();
    if (grp == 0)
        g_rpart[(b * 16 + chunk) * M + m] = part[0][m] + part[1][m] + part[2][m] + part[3][m];

    // ---- fused decoder (last chunk-block of this batch) ----
    __threadfence();
    __syncthreads();
    if (t == 0) {
        int cpl = atomicAdd(&g_cnt3[b], 1);
        isLast = (cpl == 15);
        if (cpl == 15) g_cnt3[b] = 0;
    }
    __syncthreads();
    if (!isLast) return;
    __threadfence();

    xsd[t] = g_xm[b * H + t];
    if (t < M) {
        float s = 0.f;
        for (int c = 0; c < 16; c++) s += g_rpart[(b * 16 + c) * M + t];
        rs[t] = s;
    }
    __syncthreads();
    if (t < OUT) {
        float acc2 = decb[t];
        for (int hh = 0; hh < H; hh++) acc2 = fmaf(xsd[hh], decW[hh * OUT + t], acc2);
        for (int mm = 0; mm < M; mm++) acc2 = fmaf(rs[mm], decW[(H + mm) * OUT + t], acc2);
        out[b * OUT + t] = acc2;
    }
}

// ---------------- launch ----------------
extern "C" void kernel_launch(void* const* d_in, const int* in_sizes, int n_in,
                              void* d_out, int out_size)
{
    const float* x      = (const float*)d_in[0];
    const float* r0     = (const float*)d_in[1];
    const float* sr0    = (const float*)d_in[2];
    const float* si0    = (const float*)d_in[3];
    const float* w_r0   = (const float*)d_in[4];
    const float* w_w0   = (const float*)d_in[5];
    const float* mem    = (const float*)d_in[6];
    const float* encW   = (const float*)d_in[7];
    const float* encb   = (const float*)d_in[8];
    const float* log_dt = (const float*)d_in[9];
    const float* logAr  = (const float*)d_in[10];
    const float* Aim    = (const float*)d_in[11];
    const float* Cre    = (const float*)d_in[12];
    const float* Cim    = (const float*)d_in[13];
    const float* Dv     = (const float*)d_in[14];
    const float* decW   = (const float*)d_in[15];
    const float* decb   = (const float*)d_in[16];
    const float* readW  = (const float*)d_in[17];
    const float* readb  = (const float*)d_in[18];
    const float* writeW = (const float*)d_in[19];
    const float* writeb = (const float*)d_in[20];
    float* out = (float*)d_out;

    k_encode_scan<<<dim3(B, H / 16), 256>>>(x, r0, sr0, si0, encW, encb,
                                            log_dt, logAr, Aim, Cre, Cim, Dv,
                                            writeW, writeb, readW, readb);
    k_score_addr<<<B * NMEM / 8, 256>>>(mem, w_w0, 0);
    k_score_addr<<<B * NMEM / 8, 256>>>(mem, w_r0, 1);
    k_readvec_dec<<<dim3(B, 16), 256>>>(mem, decW, decb, out);
}

// round 3
// speedup vs baseline: 1.5840x; 1.5840x over previous
#include <cuda_runtime.h>
#include <math.h>

#define B 32
#define L 256
#define EXT 64
#define H 256
#define M 64
#define NMEM 4096
#define NST 32
#define OUT 64

typedef unsigned long long ull;

// ---------------- scratch (device globals; no allocation) ----------------
__device__ float g_xm[B * H];
__device__ float g_kw[B * M], g_e[B * M], g_a[B * M], g_kr[B * M];
__device__ float g_pw[B * 8], g_pr[B * 8];
__device__ float g_score[B * NMEM];
__device__ float g_ww[B * NMEM], g_wr[B * NMEM];
__device__ float g_rpart[B * 32 * M];

// ---------------- helpers ----------------
__device__ __forceinline__ float wredsum(float v) {
    #pragma unroll
    for (int o = 16; o > 0; o >>= 1) v += __shfl_xor_sync(0xffffffffu, v, o);
    return v;
}
__device__ __forceinline__ float gredsum16(float v) {
    #pragma unroll
    for (int o = 8; o > 0; o >>= 1) v += __shfl_xor_sync(0xffffffffu, v, o);
    return v;
}
__device__ __forceinline__ float wredmax(float v) {
    #pragma unroll
    for (int o = 16; o > 0; o >>= 1) v = fmaxf(v, __shfl_xor_sync(0xffffffffu, v, o));
    return v;
}
__device__ __forceinline__ float softplus_f(float x) {
    return (x > 20.f) ? x : log1pf(expf(x));
}
__device__ __forceinline__ float sigmoid_f(float x) {
    return 1.f / (1.f + expf(-x));
}
__device__ __forceinline__ ull pack2(float lo, float hi) {
    ull r; asm("mov.b64 %0,{%1,%2};" : "=l"(r) : "f"(lo), "f"(hi)); return r;
}
__device__ __forceinline__ void unpack2(ull v, float& lo, float& hi) {
    asm("mov.b64 {%0,%1},%2;" : "=f"(lo), "=f"(hi) : "l"(v));
}
__device__ __forceinline__ ull f2fma(ull a, ull b, ull c) {
    ull d; asm("fma.rn.f32x2 %0,%1,%2,%3;" : "=l"(d) : "l"(a), "l"(b), "l"(c)); return d;
}
__device__ __forceinline__ ull f2mul(ull a, ull b) {
    ull d; asm("mul.rn.f32x2 %0,%1,%2;" : "=l"(d) : "l"(a), "l"(b)); return d;
}

// ============ Kernel 1: encoder GEMM + S4D (closed-form sum) ============
// grid (B, H/16), block 256. Warp handles 2 heads, 16-lane half packs 2 states/lane.
__global__ void __launch_bounds__(256) k_encode_scan(
    const float* __restrict__ x, const float* __restrict__ r0,
    const float* __restrict__ sr0, const float* __restrict__ si0,
    const float* __restrict__ encW, const float* __restrict__ encb,
    const float* __restrict__ log_dt, const float* __restrict__ logAr,
    const float* __restrict__ Aim, const float* __restrict__ Cre,
    const float* __restrict__ Cim, const float* __restrict__ Dv)
{
    __shared__ float xsT[64 * 66];
    __shared__ ull   Wd[128 * 16];
    __shared__ ull   us2[16 * 64];

    int b = blockIdx.x, hg = blockIdx.y;
    int t = threadIdx.x, w = t >> 5, lane = t & 31;
    int sel = lane >> 4, p = lane & 15;
    int slot = w * 2 + sel;
    int h = hg * 16 + slot;

    for (int i = t; i < 128 * 16; i += 256) {
        int e = i >> 4, sl = i & 15;
        float wv = encW[e * H + hg * 16 + sl];
        Wd[i] = pack2(wv, wv);
    }
    __syncthreads();

    float c = 0.f;
    #pragma unroll
    for (int m = p; m < M; m += 16) {
        float lo, hi; unpack2(Wd[(EXT + m) * 16 + slot], lo, hi);
        c += r0[b * M + m] * lo;
    }
    c = gredsum16(c) + encb[h];
    ull cdup = pack2(c, c);

    int n0 = 2 * p;
    float dt = expf(log_dt[h]);
    float dAr_s[2], dAi_s[2];
    #pragma unroll
    for (int s = 0; s < 2; s++) {
        int idx = h * NST + n0 + s;
        float ar = -expf(logAr[idx]);
        float ai = Aim[idx];
        float er = expf(dt * ar);
        dAr_s[s] = er * cosf(dt * ai);
        dAi_s[s] = er * sinf(dt * ai);
    }
    ull dAr2  = pack2(dAr_s[0], dAr_s[1]);
    ull dAi2  = pack2(dAi_s[0], dAi_s[1]);
    ull ndAi2 = pack2(-dAi_s[0], -dAi_s[1]);

    ull tr2 = 0, ti2 = 0;
    float usum = 0.f;
    int base = slot * 64;

    for (int ch = 0; ch < 4; ch++) {
        __syncthreads();
        int l0 = ch * 64;
        for (int i = t; i < 64 * 64; i += 256) {
            int rr = i >> 6, cc = i & 63;
            xsT[cc * 66 + rr] = x[((b * L) + (l0 + rr)) * EXT + cc];
        }
        __syncthreads();

        #pragma unroll
        for (int q = 0; q < 2; q++) {
            int pp = p + 16 * q;
            ull acc = cdup;
            #pragma unroll
            for (int e = 0; e < EXT; e++)
                acc = f2fma(Wd[e * 16 + slot],
                            *(const ull*)&xsT[e * 66 + 2 * pp], acc);
            float u0, u1; unpack2(acc, u0, u1);
            us2[base + 2 * pp]     = pack2(u0, u0);
            us2[base + 2 * pp + 1] = pack2(u1, u1);
            usum += u0 + u1;
        }
        __syncwarp();

        #pragma unroll 8
        for (int j = 0; j < 64; j++) {
            ull u2 = us2[base + j];
            ull tA = f2fma(ndAi2, ti2, u2);
            ull trn = f2fma(dAr2, tr2, tA);
            ull tB = f2mul(dAr2, ti2);
            ti2 = f2fma(dAi2, tr2, tB);
            tr2 = trn;
        }
        __syncwarp();
    }

    usum = gredsum16(usum);

    float Trp[2], Tip[2];
    unpack2(tr2, Trp[0], Trp[1]);
    unpack2(ti2, Tip[0], Tip[1]);
    float val = 0.f;
    #pragma unroll
    for (int s = 0; s < 2; s++) {
        int idx = h * NST + n0 + s;
        float ar = -expf(logAr[idx]);
        float ai = Aim[idx];
        float dar = dAr_s[s], dai = dAi_s[s];
        float xr = dar * Trp[s] - dai * Tip[s];
        float xi = dai * Trp[s] + dar * Tip[s];
        float wr = usum - xr, wi = -xi;
        float den = ar * ar + ai * ai;
        float invr = -ar / den, invi = ai / den;
        float Sr = invr * wr - invi * wi;
        float Si = invr * wi + invi * wr;
        float s0r = sr0[b * H * NST + idx], s0i = si0[b * H * NST + idx];
        if (s0r != 0.f || s0i != 0.f) {
            float eL = expf((float)L * dt * ar);
            float phi = (float)L * dt * ai;
            float dALr = eL * cosf(phi), dALi = eL * sinf(phi);
            float numr = 1.f - dALr, numi = -dALi;
            float omr = 1.f - dar, omi = -dai;
            float r2 = omr * omr + omi * omi;
            float qr = (numr * omr + numi * omi) / r2;
            float qi = (numi * omr - numr * omi) / r2;
            float gr = dar * qr - dai * qi;
            float gi = dai * qr + dar * qi;
            Sr += gr * s0r - gi * s0i;
            Si += gr * s0i + gi * s0r;
        }
        val += Cre[idx] * Sr - Cim[idx] * Si;
    }
    val = gredsum16(val);
    if (p == 0)
        g_xm[b * H + h] = (2.f * val + (Dv[h] + 1.f) * usum) * (1.f / (float)L);
}

// ============ Kernel 2: head projections ============
// grid (B), block 288
__global__ void k_heads(
    const float* __restrict__ writeW, const float* __restrict__ writeb,
    const float* __restrict__ readW,  const float* __restrict__ readb)
{
    __shared__ float xs[H];
    __shared__ float sow[3 * M + 6];
    __shared__ float sorh[M + 6];
    int b = blockIdx.x, t = threadIdx.x;
    if (t < H) xs[t] = g_xm[b * H + t];
    __syncthreads();

    if (t < 198) {
        float acc = writeb[t];
        for (int hh = 0; hh < H; hh++) acc = fmaf(xs[hh], writeW[hh * 198 + t], acc);
        sow[t] = acc;
    } else if (t < 268) {
        int j = t - 198;
        float acc = readb[j];
        for (int hh = 0; hh < H; hh++) acc = fmaf(xs[hh], readW[hh * 70 + j], acc);
        sorh[j] = acc;
    }
    __syncthreads();

    if (t < M) {
        g_kw[b * M + t] = sow[t];
        g_e[b * M + t]  = sigmoid_f(sow[M + 6 + t]);
        g_a[b * M + t]  = sow[2 * M + 6 + t];
        g_kr[b * M + t] = sorh[t];
    } else if (t == M) {
        float beta = softplus_f(sow[M]);
        float g    = sigmoid_f(sow[M + 1]);
        float m3 = fmaxf(sow[M + 2], fmaxf(sow[M + 3], sow[M + 4]));
        float e0 = expf(sow[M + 2] - m3), e1 = expf(sow[M + 3] - m3), e2 = expf(sow[M + 4] - m3);
        float Z = e0 + e1 + e2;
        float gamma = 1.f + softplus_f(sow[M + 5]);
        float nk = 0.f;
        for (int m = 0; m < M; m++) { float v = sow[m]; nk += v * v; }
        g_pw[b * 8 + 0] = beta; g_pw[b * 8 + 1] = g;
        g_pw[b * 8 + 2] = e0 / Z; g_pw[b * 8 + 3] = e1 / Z; g_pw[b * 8 + 4] = e2 / Z;
        g_pw[b * 8 + 5] = gamma; g_pw[b * 8 + 6] = sqrtf(nk);
    } else if (t == M + 1) {
        float beta = softplus_f(sorh[M]);
        float g    = sigmoid_f(sorh[M + 1]);
        float m3 = fmaxf(sorh[M + 2], fmaxf(sorh[M + 3], sorh[M + 4]));
        float e0 = expf(sorh[M + 2] - m3), e1 = expf(sorh[M + 3] - m3), e2 = expf(sorh[M + 4] - m3);
        float Z = e0 + e1 + e2;
        float gamma = 1.f + softplus_f(sorh[M + 5]);
        float nk = 0.f;
        for (int m = 0; m < M; m++) { float v = sorh[m]; nk += v * v; }
        g_pr[b * 8 + 0] = beta; g_pr[b * 8 + 1] = g;
        g_pr[b * 8 + 2] = e0 / Z; g_pr[b * 8 + 3] = e1 / Z; g_pr[b * 8 + 4] = e2 / Z;
        g_pr[b * 8 + 5] = gamma; g_pr[b * 8 + 6] = sqrtf(nk);
    }
}

// ============ Kernel 3: cosine scores, thread-per-row float4 streaming ============
// grid 512 (16 blocks per batch), block 256 -> 256 rows per block
__global__ void __launch_bounds__(256) k_score(const float* __restrict__ mem, int mode)
{
    __shared__ float ks[M], es[M], as_[M];
    int t = threadIdx.x;
    int b = blockIdx.x >> 4;            // 16 blocks per batch
    int row = blockIdx.x * 256 + t;

    const float* kptr = mode ? (g_kr + b * M) : (g_kw + b * M);
    if (t < M) {
        ks[t] = kptr[t];
        if (mode) { es[t] = g_e[b * M + t]; as_[t] = g_a[b * M + t]; }
    }
    __syncthreads();

    float wv = mode ? g_ww[row] : 0.f;
    const float4* mp = (const float4*)(mem + (size_t)row * M);
    float dot = 0.f, ss = 0.f;
    #pragma unroll
    for (int i = 0; i < 16; i++) {
        float4 v = mp[i];
        if (mode) {
            int m = i * 4;
            v.x = v.x * (1.f - wv * es[m])     + wv * as_[m];
            v.y = v.y * (1.f - wv * es[m + 1]) + wv * as_[m + 1];
            v.z = v.z * (1.f - wv * es[m + 2]) + wv * as_[m + 2];
            v.w = v.w * (1.f - wv * es[m + 3]) + wv * as_[m + 3];
        }
        int m = i * 4;
        dot = fmaf(v.x, ks[m],     dot);
        dot = fmaf(v.y, ks[m + 1], dot);
        dot = fmaf(v.z, ks[m + 2], dot);
        dot = fmaf(v.w, ks[m + 3], dot);
        ss = fmaf(v.x, v.x, ss);
        ss = fmaf(v.y, v.y, ss);
        ss = fmaf(v.z, v.z, ss);
        ss = fmaf(v.w, v.w, ss);
    }
    const float* pp = mode ? g_pr : g_pw;
    float beta = pp[b * 8 + 0], kn = pp[b * 8 + 6];
    g_score[row] = beta * dot / (sqrtf(ss) * kn + 1e-16f);
}

// ============ Kernel 4: softmax + interpolate + shift + sharpen (fast math) ============
// grid (B), block 1024
__global__ void __launch_bounds__(1024) k_address(const float* __restrict__ wprev, int mode)
{
    __shared__ float sc[NMEM];
    __shared__ float wg[NMEM];
    __shared__ float red[32];
    __shared__ float bcast;
    int b = blockIdx.x, t = threadIdx.x;
    const float* p = mode ? g_pr : g_pw;
    float g = p[b * 8 + 1], s0 = p[b * 8 + 2], s1 = p[b * 8 + 3], s2 = p[b * 8 + 4];
    float gamma = p[b * 8 + 5];
    int lane = t & 31, w = t >> 5;

    float lm = __int_as_float(0xff800000);
    #pragma unroll
    for (int i = 0; i < 4; i++) {
        int n = t + 1024 * i;
        float v = g_score[b * NMEM + n];
        sc[n] = v; lm = fmaxf(lm, v);
    }
    lm = wredmax(lm);
    if (lane == 0) red[w] = lm;
    __syncthreads();
    if (w == 0) { float v = red[lane]; v = wredmax(v); if (lane == 0) bcast = v; }
    __syncthreads();
    float bm = bcast;

    float ls = 0.f;
    #pragma unroll
    for (int i = 0; i < 4; i++) {
        int n = t + 1024 * i;
        float pv = __expf(sc[n] - bm);
        sc[n] = pv; ls += pv;
    }
    ls = wredsum(ls);
    if (lane == 0) red[w] = ls;
    __syncthreads();
    if (w == 0) { float v = red[lane]; v = wredsum(v); if (lane == 0) bcast = v; }
    __syncthreads();
    float gZ = g / bcast, og = 1.f - g;

    #pragma unroll
    for (int i = 0; i < 4; i++) {
        int n = t + 1024 * i;
        wg[n] = fmaf(gZ, sc[n], og * wprev[b * NMEM + n]);
    }
    __syncthreads();

    float lp = 0.f;
    #pragma unroll
    for (int i = 0; i < 4; i++) {
        int n = t + 1024 * i;
        float wt = s0 * wg[(n - 1) & (NMEM - 1)] + s1 * wg[n] + s2 * wg[(n + 1) & (NMEM - 1)];
        float wp = (wt > 0.f) ? __powf(wt, gamma) : 0.f;
        sc[n] = wp; lp += wp;
    }
    lp = wredsum(lp);
    if (lane == 0) red[w] = lp;
    __syncthreads();
    if (w == 0) { float v = red[lane]; v = wredsum(v); if (lane == 0) bcast = v + 1e-16f; }
    __syncthreads();
    float iZp = 1.f / bcast;

    float* wout = mode ? g_wr : g_ww;
    #pragma unroll
    for (int i = 0; i < 4; i++) {
        int n = t + 1024 * i;
        wout[b * NMEM + n] = sc[n] * iZp;
    }
}

// ============ Kernel 5: r partials = w_r . mem2, float4 + deep unroll ============
// grid (B, 32), block 256 -> 128 rows per block, thread does 8 rows of one float4 col
__global__ void __launch_bounds__(256) k_readvec(const float* __restrict__ mem)
{
    __shared__ float es4[M], as4[M];
    __shared__ float part[16][M + 4];
    int b = blockIdx.x, chunk = blockIdx.y;
    int t = threadIdx.x;
    int m4 = t & 15;            // which float4 column (m = m4*4 .. m4*4+3)
    int rgrp = t >> 4;          // 0..15 row groups
    if (t < M) { es4[t] = g_e[b * M + t]; as4[t] = g_a[b * M + t]; }
    __syncthreads();

    int m = m4 * 4;
    float4 ev = make_float4(es4[m], es4[m + 1], es4[m + 2], es4[m + 3]);
    float4 av = make_float4(as4[m], as4[m + 1], as4[m + 2], as4[m + 3]);

    float4 acc = make_float4(0.f, 0.f, 0.f, 0.f);
    int n0 = chunk * 128;
    #pragma unroll
    for (int k = 0; k < 8; k++) {
        int n = n0 + rgrp + 16 * k;
        int row = b * NMEM + n;
        float wwv = g_ww[row], wrv = g_wr[row];
        float4 v = *(const float4*)(mem + (size_t)row * M + m);
        float4 v2;
        v2.x = fmaf(v.x, 1.f - wwv * ev.x, wwv * av.x);
        v2.y = fmaf(v.y, 1.f - wwv * ev.y, wwv * av.y);
        v2.z = fmaf(v.z, 1.f - wwv * ev.z, wwv * av.z);
        v2.w = fmaf(v.w, 1.f - wwv * ev.w, wwv * av.w);
        acc.x = fmaf(wrv, v2.x, acc.x);
        acc.y = fmaf(wrv, v2.y, acc.y);
        acc.z = fmaf(wrv, v2.z, acc.z);
        acc.w = fmaf(wrv, v2.w, acc.w);
    }
    *(float4*)&part[rgrp][m] = acc;
    __syncthreads();

    if (t < M) {
        float s = 0.f;
        #pragma unroll
        for (int r = 0; r < 16; r++) s += part[r][t];
        g_rpart[(b * 32 + chunk) * M + t] = s;
    }
}

// ============ Kernel 6: decoder ============
// grid (B), block 256
__global__ void k_decode(const float* __restrict__ decW, const float* __restrict__ decb,
                         float* __restrict__ out)
{
    __shared__ float xs[H];
    __shared__ float rs[M];
    int b = blockIdx.x, t = threadIdx.x;
    xs[t] = g_xm[b * H + t];
    if (t < M) {
        float s = 0.f;
        #pragma unroll
        for (int c = 0; c < 32; c++) s += g_rpart[(b * 32 + c) * M + t];
        rs[t] = s;
    }
    __syncthreads();
    if (t < OUT) {
        float acc = decb[t];
        for (int hh = 0; hh < H; hh++) acc = fmaf(xs[hh], decW[hh * OUT + t], acc);
        for (int m = 0; m < M; m++) acc = fmaf(rs[m], decW[(H + m) * OUT + t], acc);
        out[b * OUT + t] = acc;
    }
}

// ---------------- launch ----------------
extern "C" void kernel_launch(void* const* d_in, const int* in_sizes, int n_in,
                              void* d_out, int out_size)
{
    const float* x      = (const float*)d_in[0];
    const float* r0     = (const float*)d_in[1];
    const float* sr0    = (const float*)d_in[2];
    const float* si0    = (const float*)d_in[3];
    const float* w_r0   = (const float*)d_in[4];
    const float* w_w0   = (const float*)d_in[5];
    const float* mem    = (const float*)d_in[6];
    const float* encW   = (const float*)d_in[7];
    const float* encb   = (const float*)d_in[8];
    const float* log_dt = (const float*)d_in[9];
    const float* logAr  = (const float*)d_in[10];
    const float* Aim    = (const float*)d_in[11];
    const float* Cre    = (const float*)d_in[12];
    const float* Cim    = (const float*)d_in[13];
    const float* Dv     = (const float*)d_in[14];
    const float* decW   = (const float*)d_in[15];
    const float* decb   = (const float*)d_in[16];
    const float* readW  = (const float*)d_in[17];
    const float* readb  = (const float*)d_in[18];
    const float* writeW = (const float*)d_in[19];
    const float* writeb = (const float*)d_in[20];
    float* out = (float*)d_out;

    k_encode_scan<<<dim3(B, H / 16), 256>>>(x, r0, sr0, si0, encW, encb,
                                            log_dt, logAr, Aim, Cre, Cim, Dv);
    k_heads<<<B, 288>>>(writeW, writeb, readW, readb);
    k_score<<<512, 256>>>(mem, 0);
    k_address<<<B, 1024>>>(w_w0, 0);
    k_score<<<512, 256>>>(mem, 1);
    k_address<<<B, 1024>>>(w_r0, 1);
    k_readvec<<<dim3(B, 32), 256>>>(mem);
    k_decode<<<B, 256>>>(decW, decb, out);
}

// round 6
// speedup vs baseline: 2.0684x; 1.3058x over previous
#include <cuda_runtime.h>
#include <math.h>

#define B 32
#define L 256
#define EXT 64
#define H 256
#define M 64
#define NMEM 4096
#define NST 32
#define OUT 64

typedef unsigned long long ull;

// ---------------- scratch (device globals; no allocation) ----------------
__device__ float g_xm[B * H];
__device__ float g_kw[B * M], g_e[B * M], g_a[B * M], g_kr[B * M];
__device__ float g_pw[B * 8], g_pr[B * 8];
__device__ float g_score[B * NMEM];
__device__ float g_st[7][B * NMEM];    // d1,d2,ss,s2,s3,s4,s5
__device__ float g_ww[B * NMEM], g_wr[B * NMEM];
__device__ float g_rpart[B * 32 * M];

// ---------------- helpers ----------------
__device__ __forceinline__ float wredsum(float v) {
    #pragma unroll
    for (int o = 16; o > 0; o >>= 1) v += __shfl_xor_sync(0xffffffffu, v, o);
    return v;
}
__device__ __forceinline__ float gredsum16(float v) {
    #pragma unroll
    for (int o = 8; o > 0; o >>= 1) v += __shfl_xor_sync(0xffffffffu, v, o);
    return v;
}
__device__ __forceinline__ float wredmax(float v) {
    #pragma unroll
    for (int o = 16; o > 0; o >>= 1) v = fmaxf(v, __shfl_xor_sync(0xffffffffu, v, o));
    return v;
}
__device__ __forceinline__ float softplus_f(float x) {
    return (x > 20.f) ? x : log1pf(expf(x));
}
__device__ __forceinline__ float sigmoid_f(float x) {
    return 1.f / (1.f + expf(-x));
}
__device__ __forceinline__ ull pack2(float lo, float hi) {
    ull r; asm("mov.b64 %0,{%1,%2};" : "=l"(r) : "f"(lo), "f"(hi)); return r;
}
__device__ __forceinline__ void unpack2(ull v, float& lo, float& hi) {
    asm("mov.b64 {%0,%1},%2;" : "=f"(lo), "=f"(hi) : "l"(v));
}
__device__ __forceinline__ ull f2fma(ull a, ull b, ull c) {
    ull d; asm("fma.rn.f32x2 %0,%1,%2,%3;" : "=l"(d) : "l"(a), "l"(b), "l"(c)); return d;
}
__device__ __forceinline__ ull f2mul(ull a, ull b) {
    ull d; asm("mul.rn.f32x2 %0,%1,%2;" : "=l"(d) : "l"(a), "l"(b)); return d;
}

// ============ Kernel 1: encoder GEMM + S4D (closed-form sum) ============
__global__ void __launch_bounds__(256) k_encode_scan(
    const float* __restrict__ x, const float* __restrict__ r0,
    const float* __restrict__ sr0, const float* __restrict__ si0,
    const float* __restrict__ encW, const float* __restrict__ encb,
    const float* __restrict__ log_dt, const float* __restrict__ logAr,
    const float* __restrict__ Aim, const float* __restrict__ Cre,
    const float* __restrict__ Cim, const float* __restrict__ Dv)
{
    __shared__ float xsT[64 * 66];
    __shared__ ull   Wd[128 * 16];
    __shared__ ull   us2[16 * 64];

    int b = blockIdx.x, hg = blockIdx.y;
    int t = threadIdx.x, w = t >> 5, lane = t & 31;
    int sel = lane >> 4, p = lane & 15;
    int slot = w * 2 + sel;
    int h = hg * 16 + slot;

    for (int i = t; i < 128 * 16; i += 256) {
        int e = i >> 4, sl = i & 15;
        float wv = encW[e * H + hg * 16 + sl];
        Wd[i] = pack2(wv, wv);
    }
    __syncthreads();

    float c = 0.f;
    #pragma unroll
    for (int m = p; m < M; m += 16) {
        float lo, hi; unpack2(Wd[(EXT + m) * 16 + slot], lo, hi);
        c += r0[b * M + m] * lo;
    }
    c = gredsum16(c) + encb[h];
    ull cdup = pack2(c, c);

    int n0 = 2 * p;
    float dt = expf(log_dt[h]);
    float dAr_s[2], dAi_s[2];
    #pragma unroll
    for (int s = 0; s < 2; s++) {
        int idx = h * NST + n0 + s;
        float ar = -expf(logAr[idx]);
        float ai = Aim[idx];
        float er = expf(dt * ar);
        dAr_s[s] = er * cosf(dt * ai);
        dAi_s[s] = er * sinf(dt * ai);
    }
    ull dAr2  = pack2(dAr_s[0], dAr_s[1]);
    ull dAi2  = pack2(dAi_s[0], dAi_s[1]);
    ull ndAi2 = pack2(-dAi_s[0], -dAi_s[1]);

    ull tr2 = 0, ti2 = 0;
    float usum = 0.f;
    int base = slot * 64;

    for (int ch = 0; ch < 4; ch++) {
        __syncthreads();
        int l0 = ch * 64;
        for (int i = t; i < 64 * 64; i += 256) {
            int rr = i >> 6, cc = i & 63;
            xsT[cc * 66 + rr] = x[((b * L) + (l0 + rr)) * EXT + cc];
        }
        __syncthreads();

        // GEMM: lane computes u for l-pairs 2p and 2(p+16); shared Wd load
        {
            ull acc0 = cdup, acc1 = cdup;
            #pragma unroll
            for (int e = 0; e < EXT; e++) {
                ull wv = Wd[e * 16 + slot];
                acc0 = f2fma(wv, *(const ull*)&xsT[e * 66 + 2 * p], acc0);
                acc1 = f2fma(wv, *(const ull*)&xsT[e * 66 + 2 * (p + 16)], acc1);
            }
            float u0, u1; unpack2(acc0, u0, u1);
            us2[base + 2 * p]     = pack2(u0, u0);
            us2[base + 2 * p + 1] = pack2(u1, u1);
            usum += u0 + u1;
            unpack2(acc1, u0, u1);
            us2[base + 2 * (p + 16)]     = pack2(u0, u0);
            us2[base + 2 * (p + 16) + 1] = pack2(u1, u1);
            usum += u0 + u1;
        }
        __syncwarp();

        #pragma unroll 8
        for (int j = 0; j < 64; j++) {
            ull u2 = us2[base + j];
            ull tA = f2fma(ndAi2, ti2, u2);
            ull trn = f2fma(dAr2, tr2, tA);
            ull tB = f2mul(dAr2, ti2);
            ti2 = f2fma(dAi2, tr2, tB);
            tr2 = trn;
        }
        __syncwarp();
    }

    usum = gredsum16(usum);

    float Trp[2], Tip[2];
    unpack2(tr2, Trp[0], Trp[1]);
    unpack2(ti2, Tip[0], Tip[1]);
    float val = 0.f;
    #pragma unroll
    for (int s = 0; s < 2; s++) {
        int idx = h * NST + n0 + s;
        float ar = -expf(logAr[idx]);
        float ai = Aim[idx];
        float dar = dAr_s[s], dai = dAi_s[s];
        float xr = dar * Trp[s] - dai * Tip[s];
        float xi = dai * Trp[s] + dar * Tip[s];
        float wr = usum - xr, wi = -xi;
        float den = ar * ar + ai * ai;
        float invr = -ar / den, invi = ai / den;
        float Sr = invr * wr - invi * wi;
        float Si = invr * wi + invi * wr;
        float s0r = sr0[b * H * NST + idx], s0i = si0[b * H * NST + idx];
        if (s0r != 0.f || s0i != 0.f) {
            float eL = expf((float)L * dt * ar);
            float phi = (float)L * dt * ai;
            float dALr = eL * cosf(phi), dALi = eL * sinf(phi);
            float numr = 1.f - dALr, numi = -dALi;
            float omr = 1.f - dar, omi = -dai;
            float r2 = omr * omr + omi * omi;
            float qr = (numr * omr + numi * omi) / r2;
            float qi = (numi * omr - numr * omi) / r2;
            float gr = dar * qr - dai * qi;
            float gi = dai * qr + dar * qi;
            Sr += gr * s0r - gi * s0i;
            Si += gr * s0i + gi * s0r;
        }
        val += Cre[idx] * Sr - Cim[idx] * Si;
    }
    val = gredsum16(val);
    if (p == 0)
        g_xm[b * H + h] = (2.f * val + (Dv[h] + 1.f) * usum) * (1.f / (float)L);
}

// ============ Kernel 2: head projections + per-batch consts ============
__global__ void k_heads(
    const float* __restrict__ writeW, const float* __restrict__ writeb,
    const float* __restrict__ readW,  const float* __restrict__ readb)
{
    __shared__ float xs[H];
    __shared__ float sow[3 * M + 6];
    __shared__ float sorh[M + 6];
    int b = blockIdx.x, t = threadIdx.x;
    if (t < H) xs[t] = g_xm[b * H + t];
    __syncthreads();

    if (t < 198) {
        float acc = writeb[t];
        for (int hh = 0; hh < H; hh++) acc = fmaf(xs[hh], writeW[hh * 198 + t], acc);
        sow[t] = acc;
    } else if (t < 268) {
        int j = t - 198;
        float acc = readb[j];
        for (int hh = 0; hh < H; hh++) acc = fmaf(xs[hh], readW[hh * 70 + j], acc);
        sorh[j] = acc;
    }
    __syncthreads();

    if (t < M) {
        g_kw[b * M + t] = sow[t];
        g_e[b * M + t]  = sigmoid_f(sow[M + 6 + t]);
        g_a[b * M + t]  = sow[2 * M + 6 + t];
        g_kr[b * M + t] = sorh[t];
    } else if (t == M) {
        float beta = softplus_f(sow[M]);
        float g    = sigmoid_f(sow[M + 1]);
        float m3 = fmaxf(sow[M + 2], fmaxf(sow[M + 3], sow[M + 4]));
        float e0 = expf(sow[M + 2] - m3), e1 = expf(sow[M + 3] - m3), e2 = expf(sow[M + 4] - m3);
        float Z = e0 + e1 + e2;
        float gamma = 1.f + softplus_f(sow[M + 5]);
        float nk = 0.f;
        for (int m = 0; m < M; m++) { float v = sow[m]; nk += v * v; }
        g_pw[b * 8 + 0] = beta; g_pw[b * 8 + 1] = g;
        g_pw[b * 8 + 2] = e0 / Z; g_pw[b * 8 + 3] = e1 / Z; g_pw[b * 8 + 4] = e2 / Z;
        g_pw[b * 8 + 5] = gamma; g_pw[b * 8 + 6] = sqrtf(nk);
    } else if (t == M + 1) {
        float beta = softplus_f(sorh[M]);
        float g    = sigmoid_f(sorh[M + 1]);
        float m3 = fmaxf(sorh[M + 2], fmaxf(sorh[M + 3], sorh[M + 4]));
        float e0 = expf(sorh[M + 2] - m3), e1 = expf(sorh[M + 3] - m3), e2 = expf(sorh[M + 4] - m3);
        float Z = e0 + e1 + e2;
        float gamma = 1.f + softplus_f(sorh[M + 5]);
        float nk = 0.f;
        for (int m = 0; m < M; m++) { float v = sorh[m]; nk += v * v; }
        g_pr[b * 8 + 0] = beta; g_pr[b * 8 + 1] = g;
        g_pr[b * 8 + 2] = e0 / Z; g_pr[b * 8 + 3] = e1 / Z; g_pr[b * 8 + 4] = e2 / Z;
        g_pr[b * 8 + 5] = gamma; g_pr[b * 8 + 6] = sqrtf(nk);
    } else if (t == M + 2) {
        float akr = 0.f, aa = 0.f;
        for (int m = 0; m < M; m++) {
            float av = sow[2 * M + 6 + m];
            akr = fmaf(av, sorh[m], akr);
            aa  = fmaf(av, av, aa);
        }
        g_pr[b * 8 + 7] = akr;
        g_pw[b * 8 + 7] = aa;
    }
}

// ============ Kernel 3: single mem pass -> write score + 7 read-stats ============
// grid 512 (16 blocks/batch), block 256; thread-per-row, 16x float4
__global__ void __launch_bounds__(256) k_pass1(const float* __restrict__ mem)
{
    __shared__ float kw[M], kr_[M], ekr[M], ev[M], e2v[M], av[M], eav[M];
    int t = threadIdx.x;
    int b = blockIdx.x >> 4;
    int row = blockIdx.x * 256 + t;

    if (t < M) {
        float kwv = g_kw[b * M + t];
        float krv = g_kr[b * M + t];
        float e_  = g_e[b * M + t];
        float a_  = g_a[b * M + t];
        kw[t] = kwv; kr_[t] = krv; ekr[t] = e_ * krv;
        ev[t] = e_; e2v[t] = e_ * e_; av[t] = a_; eav[t] = e_ * a_;
    }
    __syncthreads();

    const float4* mp = (const float4*)(mem + (size_t)row * M);
    float dw = 0.f, ss = 0.f, d1 = 0.f, d2 = 0.f, s2 = 0.f, s3 = 0.f, s4 = 0.f, s5 = 0.f;
    #pragma unroll
    for (int i = 0; i < 16; i++) {
        float4 v = mp[i];
        int m = i * 4;
        #pragma unroll
        for (int j = 0; j < 4; j++) {
            float vv = (&v.x)[j];
            int mm = m + j;
            float v2 = vv * vv;
            dw = fmaf(vv, kw[mm],  dw);
            ss += v2;
            d1 = fmaf(vv, kr_[mm], d1);
            d2 = fmaf(vv, ekr[mm], d2);
            s2 = fmaf(v2, ev[mm],  s2);
            s3 = fmaf(v2, e2v[mm], s3);
            s4 = fmaf(vv, av[mm],  s4);
            s5 = fmaf(vv, eav[mm], s5);
        }
    }
    float beta = g_pw[b * 8 + 0], knw = g_pw[b * 8 + 6];
    g_score[row] = beta * dw / (sqrtf(ss) * knw + 1e-16f);
    g_st[0][row] = d1; g_st[1][row] = d2; g_st[2][row] = ss;
    g_st[3][row] = s2; g_st[4][row] = s3; g_st[5][row] = s4; g_st[6][row] = s5;
}

// ============ Kernel 4: write addressing + read score + read addressing ============
// grid (B), block 1024; smem = 2*NMEM*4 + 132 = ~32.9KB (fits static 48KB)
__global__ void __launch_bounds__(1024) k_addr2(
    const float* __restrict__ ww0, const float* __restrict__ wr0)
{
    __shared__ float sc[NMEM];
    __shared__ float wg[NMEM];
    __shared__ float red[32];
    __shared__ float bcast;
    int b = blockIdx.x, t = threadIdx.x;
    int lane = t & 31, w = t >> 5;

    // ======== phase A: write addressing ========
    {
        float g = g_pw[b * 8 + 1], s0 = g_pw[b * 8 + 2], s1 = g_pw[b * 8 + 3];
        float s2 = g_pw[b * 8 + 4], gamma = g_pw[b * 8 + 5];

        float lm = __int_as_float(0xff800000);
        #pragma unroll
        for (int i = 0; i < 4; i++) {
            int n = t + 1024 * i;
            float v = g_score[b * NMEM + n];
            sc[n] = v; lm = fmaxf(lm, v);
        }
        lm = wredmax(lm);
        if (lane == 0) red[w] = lm;
        __syncthreads();
        if (w == 0) { float v = red[lane]; v = wredmax(v); if (lane == 0) bcast = v; }
        __syncthreads();
        float bm = bcast;

        float ls = 0.f;
        #pragma unroll
        for (int i = 0; i < 4; i++) {
            int n = t + 1024 * i;
            float pv = __expf(sc[n] - bm);
            sc[n] = pv; ls += pv;
        }
        ls = wredsum(ls);
        if (lane == 0) red[w] = ls;
        __syncthreads();
        if (w == 0) { float v = red[lane]; v = wredsum(v); if (lane == 0) bcast = v; }
        __syncthreads();
        float gZ = g / bcast, og = 1.f - g;

        #pragma unroll
        for (int i = 0; i < 4; i++) {
            int n = t + 1024 * i;
            wg[n] = fmaf(gZ, sc[n], og * ww0[b * NMEM + n]);
        }
        __syncthreads();

        float lp = 0.f;
        #pragma unroll
        for (int i = 0; i < 4; i++) {
            int n = t + 1024 * i;
            float wt = s0 * wg[(n - 1) & (NMEM - 1)] + s1 * wg[n] + s2 * wg[(n + 1) & (NMEM - 1)];
            float wp = (wt > 0.f) ? __powf(wt, gamma) : 0.f;
            sc[n] = wp; lp += wp;
        }
        lp = wredsum(lp);
        if (lane == 0) red[w] = lp;
        __syncthreads();
        if (w == 0) { float v = red[lane]; v = wredsum(v); if (lane == 0) bcast = v + 1e-16f; }
        __syncthreads();
        float iZp = 1.f / bcast;

        #pragma unroll
        for (int i = 0; i < 4; i++) {
            int n = t + 1024 * i;
            g_ww[b * NMEM + n] = sc[n] * iZp;
        }
        __syncthreads();
    }

    // ======== phase B: read score from stats, then read addressing ========
    {
        float beta = g_pr[b * 8 + 0], knr = g_pr[b * 8 + 6];
        float akr  = g_pr[b * 8 + 7], aa  = g_pw[b * 8 + 7];
        float g = g_pr[b * 8 + 1], s0 = g_pr[b * 8 + 2], s1 = g_pr[b * 8 + 3];
        float s2p = g_pr[b * 8 + 4], gamma = g_pr[b * 8 + 5];

        float lm = __int_as_float(0xff800000);
        #pragma unroll
        for (int i = 0; i < 4; i++) {
            int n = t + 1024 * i;
            int row = b * NMEM + n;
            float wwv = g_ww[row];
            float d1 = g_st[0][row], d2 = g_st[1][row], ssv = g_st[2][row];
            float s2v = g_st[3][row], s3v = g_st[4][row], s4v = g_st[5][row], s5v = g_st[6][row];
            float dot = d1 - wwv * (d2 - akr);
            float n2 = ssv + wwv * (2.f * (s4v - s2v)) + wwv * wwv * (s3v - 2.f * s5v + aa);
            float v = beta * dot / (sqrtf(fmaxf(n2, 0.f)) * knr + 1e-16f);
            sc[n] = v; lm = fmaxf(lm, v);
        }
        lm = wredmax(lm);
        if (lane == 0) red[w] = lm;
        __syncthreads();
        if (w == 0) { float v = red[lane]; v = wredmax(v); if (lane == 0) bcast = v; }
        __syncthreads();
        float bm = bcast;

        float ls = 0.f;
        #pragma unroll
        for (int i = 0; i < 4; i++) {
            int n = t + 1024 * i;
            float pv = __expf(sc[n] - bm);
            sc[n] = pv; ls += pv;
        }
        ls = wredsum(ls);
        if (lane == 0) red[w] = ls;
        __syncthreads();
        if (w == 0) { float v = red[lane]; v = wredsum(v); if (lane == 0) bcast = v; }
        __syncthreads();
        float gZ = g / bcast, og = 1.f - g;

        #pragma unroll
        for (int i = 0; i < 4; i++) {
            int n = t + 1024 * i;
            wg[n] = fmaf(gZ, sc[n], og * wr0[b * NMEM + n]);
        }
        __syncthreads();

        float lp = 0.f;
        #pragma unroll
        for (int i = 0; i < 4; i++) {
            int n = t + 1024 * i;
            float wt = s0 * wg[(n - 1) & (NMEM - 1)] + s1 * wg[n] + s2p * wg[(n + 1) & (NMEM - 1)];
            float wp = (wt > 0.f) ? __powf(wt, gamma) : 0.f;
            sc[n] = wp; lp += wp;
        }
        lp = wredsum(lp);
        if (lane == 0) red[w] = lp;
        __syncthreads();
        if (w == 0) { float v = red[lane]; v = wredsum(v); if (lane == 0) bcast = v + 1e-16f; }
        __syncthreads();
        float iZp = 1.f / bcast;

        #pragma unroll
        for (int i = 0; i < 4; i++) {
            int n = t + 1024 * i;
            g_wr[b * NMEM + n] = sc[n] * iZp;
        }
    }
}

// ============ Kernel 5: r partials = w_r . mem2 ============
// grid (B, 32), block 256
__global__ void __launch_bounds__(256) k_readvec(const float* __restrict__ mem)
{
    __shared__ float es4[M], as4[M];
    __shared__ float part[16][M + 4];
    int b = blockIdx.x, chunk = blockIdx.y;
    int t = threadIdx.x;
    int m4 = t & 15;
    int rgrp = t >> 4;
    if (t < M) { es4[t] = g_e[b * M + t]; as4[t] = g_a[b * M + t]; }
    __syncthreads();

    int m = m4 * 4;
    float4 ev = make_float4(es4[m], es4[m + 1], es4[m + 2], es4[m + 3]);
    float4 av = make_float4(as4[m], as4[m + 1], as4[m + 2], as4[m + 3]);

    float4 acc = make_float4(0.f, 0.f, 0.f, 0.f);
    int n0 = chunk * 128;
    #pragma unroll
    for (int k = 0; k < 8; k++) {
        int n = n0 + rgrp + 16 * k;
        int row = b * NMEM + n;
        float wwv = g_ww[row], wrv = g_wr[row];
        float4 v = *(const float4*)(mem + (size_t)row * M + m);
        float4 v2;
        v2.x = fmaf(v.x, 1.f - wwv * ev.x, wwv * av.x);
        v2.y = fmaf(v.y, 1.f - wwv * ev.y, wwv * av.y);
        v2.z = fmaf(v.z, 1.f - wwv * ev.z, wwv * av.z);
        v2.w = fmaf(v.w, 1.f - wwv * ev.w, wwv * av.w);
        acc.x = fmaf(wrv, v2.x, acc.x);
        acc.y = fmaf(wrv, v2.y, acc.y);
        acc.z = fmaf(wrv, v2.z, acc.z);
        acc.w = fmaf(wrv, v2.w, acc.w);
    }
    *(float4*)&part[rgrp][m] = acc;
    __syncthreads();

    if (t < M) {
        float s = 0.f;
        #pragma unroll
        for (int r = 0; r < 16; r++) s += part[r][t];
        g_rpart[(b * 32 + chunk) * M + t] = s;
    }
}

// ============ Kernel 6: decoder ============
__global__ void k_decode(const float* __restrict__ decW, const float* __restrict__ decb,
                         float* __restrict__ out)
{
    __shared__ float xs[H];
    __shared__ float rs[M];
    int b = blockIdx.x, t = threadIdx.x;
    xs[t] = g_xm[b * H + t];
    if (t < M) {
        float s = 0.f;
        #pragma unroll
        for (int c = 0; c < 32; c++) s += g_rpart[(b * 32 + c) * M + t];
        rs[t] = s;
    }
    __syncthreads();
    if (t < OUT) {
        float acc = decb[t];
        for (int hh = 0; hh < H; hh++) acc = fmaf(xs[hh], decW[hh * OUT + t], acc);
        for (int m = 0; m < M; m++) acc = fmaf(rs[m], decW[(H + m) * OUT + t], acc);
        out[b * OUT + t] = acc;
    }
}

// ---------------- launch ----------------
extern "C" void kernel_launch(void* const* d_in, const int* in_sizes, int n_in,
                              void* d_out, int out_size)
{
    const float* x      = (const float*)d_in[0];
    const float* r0     = (const float*)d_in[1];
    const float* sr0    = (const float*)d_in[2];
    const float* si0    = (const float*)d_in[3];
    const float* w_r0   = (const float*)d_in[4];
    const float* w_w0   = (const float*)d_in[5];
    const float* mem    = (const float*)d_in[6];
    const float* encW   = (const float*)d_in[7];
    const float* encb   = (const float*)d_in[8];
    const float* log_dt = (const float*)d_in[9];
    const float* logAr  = (const float*)d_in[10];
    const float* Aim    = (const float*)d_in[11];
    const float* Cre    = (const float*)d_in[12];
    const float* Cim    = (const float*)d_in[13];
    const float* Dv     = (const float*)d_in[14];
    const float* decW   = (const float*)d_in[15];
    const float* decb   = (const float*)d_in[16];
    const float* readW  = (const float*)d_in[17];
    const float* readb  = (const float*)d_in[18];
    const float* writeW = (const float*)d_in[19];
    const float* writeb = (const float*)d_in[20];
    float* out = (float*)d_out;

    k_encode_scan<<<dim3(B, H / 16), 256>>>(x, r0, sr0, si0, encW, encb,
                                            log_dt, logAr, Aim, Cre, Cim, Dv);
    k_heads<<<B, 288>>>(writeW, writeb, readW, readb);
    k_pass1<<<512, 256>>>(mem);
    k_addr2<<<B, 1024>>>(w_w0, w_r0);
    k_readvec<<<dim3(B, 32), 256>>>(mem);
    k_decode<<<B, 256>>>(decW, decb, out);
}